// round 7
// baseline (speedup 1.0000x reference)
// QuantizedLinear: out = scale * (x @ qw^T) + bias_scale * q_bias
// M=8192, K=4096, N=16384, fp32 in/out, int32 (int8-valued) weights.
//
// sm_103 BASELINE toolchain: tcgen05 rejected, so ldmatrix + mma.sync.
// This round: exact int8 IMMA (m16n8k32.s8) — weights are already int8;
// x split as s*(x1 + x2/252) with int8 x1,x2 -> exact integer accumulation,
// rel err ~4e-5. Fragment byte layout of s8.k32 == bf16.k16, so the proven
// R5 ldmatrix/swizzle/pipeline structure is reused with NKT halved (32).
#include <cuda_runtime.h>
#include <cuda_bf16.h>
#include <cstdint>

// ---------------- problem constants ----------------
constexpr int Mdim = 8192;
constexpr int Ndim = 16384;
constexpr int Kdim = 4096;

constexpr int BM = 128;
constexpr int BN = 128;
constexpr int BKB = 128;            // 128 int8 k-elems = 128B per row per k-iter
constexpr int STAGES = 4;
constexpr int NKT = Kdim / BKB;     // 32 k-iterations

// SMEM layout (dynamic)
constexpr int OFF_BIAS  = 0;        // 128 floats
constexpr int OFF_STAGE = 1024;
constexpr int STAGE_STRIDE = 49152; // X1 16K | X2 16K | W 16K
constexpr int X1_OFF = 0;
constexpr int X2_OFF = 16384;
constexpr int W_OFF  = 32768;
constexpr int SMEM_TOTAL = OFF_STAGE + STAGES * STAGE_STRIDE; // 197632

// ---------------- device scratch (no cudaMalloc allowed) ----------------
__device__ uint4 g_w8 [(size_t)Ndim * Kdim / 16];  // 64MB int8 weights
__device__ uint4 g_x1 [(size_t)Mdim * Kdim / 16];  // 32MB int8 x-hi
__device__ uint4 g_x2 [(size_t)Mdim * Kdim / 16];  // 32MB int8 x-lo
__device__ int   g_xmax_bits;                      // zero-init; max is idempotent

// ---------------- helpers ----------------
__device__ __forceinline__ uint32_t smem_u32(const void* p) {
    uint32_t a;
    asm("{ .reg .u64 t; cvta.to.shared.u64 t, %1; cvt.u32.u64 %0, t; }" : "=r"(a) : "l"(p));
    return a;
}
// 128B-row swizzle: XOR 16B-chunk index with (row & 7)
__device__ __forceinline__ uint32_t swz(uint32_t byte_off) {
    return byte_off ^ ((byte_off >> 3) & 0x70);
}
__device__ __forceinline__ void cp16(uint32_t dst, const void* src) {
    asm volatile("cp.async.cg.shared.global [%0], [%1], 16;" :: "r"(dst), "l"(src) : "memory");
}
__device__ __forceinline__ void cp_commit() {
    asm volatile("cp.async.commit_group;" ::: "memory");
}
__device__ __forceinline__ void cp_wait2() {
    asm volatile("cp.async.wait_group 2;" ::: "memory");
}
__device__ __forceinline__ void ldsm_x4(uint32_t r[4], uint32_t addr) {
    asm volatile("ldmatrix.sync.aligned.m8n8.x4.shared.b16 {%0,%1,%2,%3}, [%4];"
                 : "=r"(r[0]), "=r"(r[1]), "=r"(r[2]), "=r"(r[3]) : "r"(addr));
}
__device__ __forceinline__ void imma16832(int c[4], const uint32_t a[4], const uint32_t b[2]) {
    asm volatile(
        "mma.sync.aligned.m16n8k32.row.col.s32.s8.s8.s32 "
        "{%0,%1,%2,%3}, {%4,%5,%6,%7}, {%8,%9}, {%0,%1,%2,%3};"
        : "+r"(c[0]), "+r"(c[1]), "+r"(c[2]), "+r"(c[3])
        : "r"(a[0]), "r"(a[1]), "r"(a[2]), "r"(a[3]), "r"(b[0]), "r"(b[1]));
}

// ---------------- preprocess kernels ----------------
__global__ void maxabs_kernel(const float* __restrict__ x) {
    const float4* x4 = reinterpret_cast<const float4*>(x);
    const size_t n4 = (size_t)Mdim * Kdim / 4;
    const size_t stride = (size_t)gridDim.x * blockDim.x;
    float m = 0.0f;
    for (size_t i = (size_t)blockIdx.x * blockDim.x + threadIdx.x; i < n4; i += stride) {
        float4 v = x4[i];
        m = fmaxf(m, fmaxf(fmaxf(fabsf(v.x), fabsf(v.y)), fmaxf(fabsf(v.z), fabsf(v.w))));
    }
    #pragma unroll
    for (int o = 16; o; o >>= 1) m = fmaxf(m, __shfl_xor_sync(0xffffffffu, m, o));
    if ((threadIdx.x & 31) == 0) atomicMax(&g_xmax_bits, __float_as_int(m));
}

__device__ __forceinline__ signed char q8(float v) {
    float r = rintf(v);
    r = fminf(fmaxf(r, -127.0f), 127.0f);
    return (signed char)(int)r;
}

__global__ void convert_x_kernel(const float* __restrict__ x) {
    const float xmax = __int_as_float(g_xmax_bits);
    const float s    = xmax / 127.0f;
    const float invs = 127.0f / xmax;
    const float inv2 = 252.0f / s;
    char4* x1p = reinterpret_cast<char4*>(g_x1);
    char4* x2p = reinterpret_cast<char4*>(g_x2);
    const float4* x4 = reinterpret_cast<const float4*>(x);
    const size_t n4 = (size_t)Mdim * Kdim / 4;
    const size_t stride = (size_t)gridDim.x * blockDim.x;
    for (size_t i = (size_t)blockIdx.x * blockDim.x + threadIdx.x; i < n4; i += stride) {
        float4 v = x4[i];
        float a0 = fminf(fmaxf(rintf(v.x * invs), -127.0f), 127.0f);
        float a1 = fminf(fmaxf(rintf(v.y * invs), -127.0f), 127.0f);
        float a2 = fminf(fmaxf(rintf(v.z * invs), -127.0f), 127.0f);
        float a3 = fminf(fmaxf(rintf(v.w * invs), -127.0f), 127.0f);
        char4 c1;
        c1.x = (signed char)(int)a0; c1.y = (signed char)(int)a1;
        c1.z = (signed char)(int)a2; c1.w = (signed char)(int)a3;
        char4 c2;
        c2.x = q8((v.x - a0 * s) * inv2);
        c2.y = q8((v.y - a1 * s) * inv2);
        c2.z = q8((v.z - a2 * s) * inv2);
        c2.w = q8((v.w - a3 * s) * inv2);
        x1p[i] = c1;
        x2p[i] = c2;
    }
}

__global__ void convert_w_kernel(const int* __restrict__ qw) {
    char4* wp = reinterpret_cast<char4*>(g_w8);
    const int4* qw4 = reinterpret_cast<const int4*>(qw);
    const size_t n4 = (size_t)Ndim * Kdim / 4;
    const size_t stride = (size_t)gridDim.x * blockDim.x;
    for (size_t i = (size_t)blockIdx.x * blockDim.x + threadIdx.x; i < n4; i += stride) {
        int4 v = qw4[i];
        char4 c;
        c.x = (signed char)v.x; c.y = (signed char)v.y;
        c.z = (signed char)v.z; c.w = (signed char)v.w;
        wp[i] = c;
    }
}

// ---------------- main GEMM kernel ----------------
__global__ void __launch_bounds__(256, 1)
gemm_kernel(const int* __restrict__ qbias,
            const float* __restrict__ scale_p,
            const float* __restrict__ bscale_p,
            float* __restrict__ out) {
    extern __shared__ char smem[];
    const uint32_t sbase = smem_u32(smem);
    const int tid  = threadIdx.x;
    const int wid  = tid >> 5;
    const int lane = tid & 31;
    const int wm = wid >> 2;   // 0..1  -> 64-row M slab
    const int wn = wid & 3;    // 0..3  -> 32-col N slab

    const signed char* x1 = reinterpret_cast<const signed char*>(g_x1);
    const signed char* x2 = reinterpret_cast<const signed char*>(g_x2);
    const signed char* wb = reinterpret_cast<const signed char*>(g_w8);

    const int n0 = blockIdx.x * BN;
    const int m0 = blockIdx.y * BM;

    // bias staging: biasS[j] = bias_scale * q_bias[n0 + j]
    {
        float bsc = bscale_p[0];
        float* sb = reinterpret_cast<float*>(smem + OFF_BIAS);
        for (int i = tid; i < BN; i += 256)
            sb[i] = bsc * (float)qbias[n0 + i];
    }

    // -------- per-thread producer address precompute --------
    // Each tile = 128 rows x 8 chunks of 16B = 1024 chunks; 256 threads x 4.
    const signed char* pX1[4];
    const signed char* pX2[4];
    const signed char* pW [4];
    uint32_t dA[4];
    #pragma unroll
    for (int i = 0; i < 4; i++) {
        int q = i * 256 + tid;
        int row = q >> 3, ch = q & 7;
        dA[i] = swz((uint32_t)(row * 128 + ch * 16));
        pX1[i] = x1 + (size_t)(m0 + row) * Kdim + ch * 16;
        pX2[i] = x2 + (size_t)(m0 + row) * Kdim + ch * 16;
        pW [i] = wb + (size_t)(n0 + row) * Kdim + ch * 16;
    }

    // -------- accumulators: two integer banks (x1-pass, x2-pass) --------
    int acc1[4][4][4];
    int acc2[4][4][4];
    #pragma unroll
    for (int mi = 0; mi < 4; mi++)
        #pragma unroll
        for (int ni = 0; ni < 4; ni++)
            #pragma unroll
            for (int j = 0; j < 4; j++) { acc1[mi][ni][j] = 0; acc2[mi][ni][j] = 0; }

    // -------- prologue: prefetch stages 0..STAGES-2 --------
    #pragma unroll
    for (int s = 0; s < STAGES - 1; s++) {
        const uint32_t sb_ = sbase + OFF_STAGE + s * STAGE_STRIDE;
        const int k0 = s * BKB;
        #pragma unroll
        for (int i = 0; i < 4; i++) {
            cp16(sb_ + X1_OFF + dA[i], pX1[i] + k0);
            cp16(sb_ + X2_OFF + dA[i], pX2[i] + k0);
            cp16(sb_ + W_OFF  + dA[i], pW [i] + k0);
        }
        cp_commit();
    }

    // -------- mainloop --------
    const int mrow_base = wm * 64;
    const int nb_base   = wn * 32;

    // ldmatrix lane-invariant pieces (verified mapping from R5 bf16 kernel;
    // s8.k32 fragments are byte-identical to bf16.k16 fragments)
    const int a_row_in  = lane & 15;
    const int a_ksel    = lane >> 4;
    const int b_nrow_in = ((lane >> 4) << 3) + (lane & 7);
    const int b_ksel    = (lane >> 3) & 1;

    int st = 0;
    for (int kt = 0; kt < NKT; kt++) {
        cp_wait2();
        __syncthreads();

        // issue loads for kt+STAGES-1 into the stage freed last iteration
        {
            int kt_next = kt + STAGES - 1;
            if (kt_next < NKT) {
                int stn = st + (STAGES - 1); if (stn >= STAGES) stn -= STAGES;
                const uint32_t sb_ = sbase + OFF_STAGE + stn * STAGE_STRIDE;
                const int k0 = kt_next * BKB;
                #pragma unroll
                for (int i = 0; i < 4; i++) {
                    cp16(sb_ + X1_OFF + dA[i], pX1[i] + k0);
                    cp16(sb_ + X2_OFF + dA[i], pX2[i] + k0);
                    cp16(sb_ + W_OFF  + dA[i], pW [i] + k0);
                }
            }
            cp_commit(); // commit (possibly empty) to keep wait counts aligned
        }

        // consume stage st
        const uint32_t sX1 = sbase + OFF_STAGE + st * STAGE_STRIDE + X1_OFF;
        const uint32_t sX2 = sbase + OFF_STAGE + st * STAGE_STRIDE + X2_OFF;
        const uint32_t sW  = sbase + OFF_STAGE + st * STAGE_STRIDE + W_OFF;

        #pragma unroll
        for (int s = 0; s < 4; s++) {          // 4 k-steps of k32 (32B each)
            // ---- W (B) fragments: 4 n-chunks of 8 ----
            uint32_t bfr[4][2];
            {
                uint32_t t[4];
                int nrow = nb_base + b_nrow_in;
                int ch = 2 * s + b_ksel;
                ldsm_x4(t, sW + (uint32_t)nrow * 128 + (uint32_t)((ch ^ (nrow & 7)) << 4));
                bfr[0][0] = t[0]; bfr[0][1] = t[1];
                bfr[1][0] = t[2]; bfr[1][1] = t[3];
                nrow += 16;
                ldsm_x4(t, sW + (uint32_t)nrow * 128 + (uint32_t)((ch ^ (nrow & 7)) << 4));
                bfr[2][0] = t[0]; bfr[2][1] = t[1];
                bfr[3][0] = t[2]; bfr[3][1] = t[3];
            }
            // ---- X1 pass then X2 pass, 4 m-chunks of 16 ----
            #pragma unroll
            for (int mi = 0; mi < 4; mi++) {
                int arow = mrow_base + mi * 16 + a_row_in;
                int ch = 2 * s + a_ksel;
                uint32_t off = (uint32_t)arow * 128 + (uint32_t)((ch ^ (arow & 7)) << 4);
                uint32_t af[4];
                ldsm_x4(af, sX1 + off);
                #pragma unroll
                for (int ni = 0; ni < 4; ni++)
                    imma16832(acc1[mi][ni], af, bfr[ni]);
                ldsm_x4(af, sX2 + off);
                #pragma unroll
                for (int ni = 0; ni < 4; ni++)
                    imma16832(acc2[mi][ni], af, bfr[ni]);
            }
        }

        st = (st + 1 == STAGES) ? 0 : st + 1;
    }

    // -------- epilogue: out = scale*s*(acc1 + acc2/252) + biasS --------
    const float xmax = __int_as_float(g_xmax_bits);
    const float cs = scale_p[0] * (xmax / 127.0f);
    constexpr float INV252 = 1.0f / 252.0f;
    const float* bs = reinterpret_cast<const float*>(smem + OFF_BIAS);
    const int gr = lane >> 2;
    const int gc = (lane & 3) * 2;
    #pragma unroll
    for (int mi = 0; mi < 4; mi++) {
        const int r = m0 + wm * 64 + mi * 16 + gr;
        #pragma unroll
        for (int ni = 0; ni < 4; ni++) {
            const int cl = wn * 32 + ni * 8 + gc;   // local col in [0,128)
            const int c  = n0 + cl;
            float t0 = (float)acc1[mi][ni][0] + (float)acc2[mi][ni][0] * INV252;
            float t1 = (float)acc1[mi][ni][1] + (float)acc2[mi][ni][1] * INV252;
            float t2 = (float)acc1[mi][ni][2] + (float)acc2[mi][ni][2] * INV252;
            float t3 = (float)acc1[mi][ni][3] + (float)acc2[mi][ni][3] * INV252;
            float2 v;
            v.x = fmaf(cs, t0, bs[cl]);
            v.y = fmaf(cs, t1, bs[cl + 1]);
            *reinterpret_cast<float2*>(out + (size_t)r * Ndim + c) = v;
            v.x = fmaf(cs, t2, bs[cl]);
            v.y = fmaf(cs, t3, bs[cl + 1]);
            *reinterpret_cast<float2*>(out + (size_t)(r + 8) * Ndim + c) = v;
        }
    }
}

// ---------------- launch ----------------
extern "C" void kernel_launch(void* const* d_in, const int* in_sizes, int n_in,
                              void* d_out, int out_size) {
    const float* x   = (const float*)d_in[0];
    const int*   qw  = (const int*)d_in[1];
    const int*   qb  = (const int*)d_in[2];
    const float* sc  = (const float*)d_in[3];
    const float* bsc = (const float*)d_in[4];
    float* out = (float*)d_out;

    maxabs_kernel<<<592, 256>>>(x);          // stream-ordered: before convert_x
    convert_x_kernel<<<1184, 256>>>(x);
    convert_w_kernel<<<1184, 256>>>(qw);

    cudaFuncSetAttribute(gemm_kernel, cudaFuncAttributeMaxDynamicSharedMemorySize, SMEM_TOTAL);
    dim3 grid(Ndim / BN, Mdim / BM); // (128, 64)
    gemm_kernel<<<grid, 256, SMEM_TOTAL>>>(qb, sc, bsc, out);
}

// round 8
// speedup vs baseline: 6.1366x; 6.1366x over previous
// QuantizedLinear: out = scale * (x @ qw^T) + bias_scale * q_bias
// M=8192, K=4096, N=16384, fp32 in/out, int32 (int8-valued) weights.
//
// sm_103 BASELINE toolchain: tcgen05 rejected by ptxas; legacy IMMA proven
// 4x slower than HMMA (R7: tensor=96% busy). This round: SINGLE fp16 pass.
// Weights are int8-valued -> exact in fp16 (11 mantissa bits); x rounded to
// fp16 gives norm rel-err ~2.5e-4 < 1e-3. Half of R5's HMMA count.
// 2 CTAs/SM (96KB smem each) to hide sync bubbles under the other CTA's MMAs.
#include <cuda_runtime.h>
#include <cuda_fp16.h>
#include <cstdint>

// ---------------- problem constants ----------------
constexpr int Mdim = 8192;
constexpr int Ndim = 16384;
constexpr int Kdim = 4096;

constexpr int BM = 128;
constexpr int BN = 128;
constexpr int BK = 64;              // 64 fp16 = 128B = one swizzle row
constexpr int STAGES = 3;
constexpr int NKT = Kdim / BK;      // 64 k-iterations

// SMEM layout (dynamic)
constexpr int OFF_BIAS  = 0;        // 128 floats
constexpr int OFF_STAGE = 1024;
constexpr int STAGE_STRIDE = 32768; // A 16K | B 16K
constexpr int A_OFF = 0;
constexpr int B_OFF = 16384;
constexpr int SMEM_TOTAL = OFF_STAGE + STAGES * STAGE_STRIDE; // 99328

// ---------------- device scratch (no cudaMalloc allowed) ----------------
__device__ uint4 g_wh[(size_t)Ndim * Kdim * 2 / 16]; // 128MB fp16 weights
__device__ uint4 g_xh[(size_t)Mdim * Kdim * 2 / 16]; //  64MB fp16 x

// ---------------- helpers ----------------
__device__ __forceinline__ uint32_t smem_u32(const void* p) {
    uint32_t a;
    asm("{ .reg .u64 t; cvta.to.shared.u64 t, %1; cvt.u32.u64 %0, t; }" : "=r"(a) : "l"(p));
    return a;
}
// 128B-row swizzle: XOR 16B-chunk index with (row & 7)
__device__ __forceinline__ uint32_t swz(uint32_t byte_off) {
    return byte_off ^ ((byte_off >> 3) & 0x70);
}
__device__ __forceinline__ void cp16(uint32_t dst, const void* src) {
    asm volatile("cp.async.cg.shared.global [%0], [%1], 16;" :: "r"(dst), "l"(src) : "memory");
}
__device__ __forceinline__ void cp_commit() {
    asm volatile("cp.async.commit_group;" ::: "memory");
}
__device__ __forceinline__ void cp_wait1() {
    asm volatile("cp.async.wait_group 1;" ::: "memory");
}
__device__ __forceinline__ void ldsm_x4(uint32_t r[4], uint32_t addr) {
    asm volatile("ldmatrix.sync.aligned.m8n8.x4.shared.b16 {%0,%1,%2,%3}, [%4];"
                 : "=r"(r[0]), "=r"(r[1]), "=r"(r[2]), "=r"(r[3]) : "r"(addr));
}
__device__ __forceinline__ void mma16816(float c[4], const uint32_t a[4], const uint32_t b[2]) {
    asm volatile(
        "mma.sync.aligned.m16n8k16.row.col.f32.f16.f16.f32 "
        "{%0,%1,%2,%3}, {%4,%5,%6,%7}, {%8,%9}, {%0,%1,%2,%3};"
        : "+f"(c[0]), "+f"(c[1]), "+f"(c[2]), "+f"(c[3])
        : "r"(a[0]), "r"(a[1]), "r"(a[2]), "r"(a[3]), "r"(b[0]), "r"(b[1]));
}

// ---------------- preconvert kernels ----------------
__global__ void convert_w_kernel(const int* __restrict__ qw) {
    __half2* wh2 = reinterpret_cast<__half2*>(g_wh);
    const int4* qw4 = reinterpret_cast<const int4*>(qw);
    const size_t n4 = (size_t)Ndim * Kdim / 4;
    const size_t stride = (size_t)gridDim.x * blockDim.x;
    for (size_t i = (size_t)blockIdx.x * blockDim.x + threadIdx.x; i < n4; i += stride) {
        int4 v = qw4[i];
        __half2 a, b;
        a.x = __float2half_rn((float)v.x);
        a.y = __float2half_rn((float)v.y);
        b.x = __float2half_rn((float)v.z);
        b.y = __float2half_rn((float)v.w);
        wh2[i * 2]     = a;
        wh2[i * 2 + 1] = b;
    }
}

__global__ void convert_x_kernel(const float* __restrict__ x) {
    __half2* xh2 = reinterpret_cast<__half2*>(g_xh);
    const float4* x4 = reinterpret_cast<const float4*>(x);
    const size_t n4 = (size_t)Mdim * Kdim / 4;
    const size_t stride = (size_t)gridDim.x * blockDim.x;
    for (size_t i = (size_t)blockIdx.x * blockDim.x + threadIdx.x; i < n4; i += stride) {
        float4 v = x4[i];
        __half2 a, b;
        a.x = __float2half_rn(v.x);
        a.y = __float2half_rn(v.y);
        b.x = __float2half_rn(v.z);
        b.y = __float2half_rn(v.w);
        xh2[i * 2]     = a;
        xh2[i * 2 + 1] = b;
    }
}

// ---------------- main GEMM kernel ----------------
__global__ void __launch_bounds__(256, 2)
gemm_kernel(const int* __restrict__ qbias,
            const float* __restrict__ scale_p,
            const float* __restrict__ bscale_p,
            float* __restrict__ out) {
    extern __shared__ char smem[];
    const uint32_t sbase = smem_u32(smem);
    const int tid  = threadIdx.x;
    const int wid  = tid >> 5;
    const int lane = tid & 31;
    const int wm = wid >> 2;   // 0..1  -> 64-row M slab
    const int wn = wid & 3;    // 0..3  -> 32-col N slab

    const __half* xh = reinterpret_cast<const __half*>(g_xh);
    const __half* wh = reinterpret_cast<const __half*>(g_wh);

    const int n0 = blockIdx.x * BN;
    const int m0 = blockIdx.y * BM;

    // bias staging: biasS[j] = bias_scale * q_bias[n0 + j]
    {
        float bsc = bscale_p[0];
        float* sb = reinterpret_cast<float*>(smem + OFF_BIAS);
        for (int i = tid; i < BN; i += 256)
            sb[i] = bsc * (float)qbias[n0 + i];
    }

    // -------- per-thread producer address precompute --------
    // Each tile = 128 rows x 8 chunks of 16B = 1024 chunks; 256 threads x 4.
    const __half* pA[4];
    const __half* pB[4];
    uint32_t dA[4];
    #pragma unroll
    for (int i = 0; i < 4; i++) {
        int q = i * 256 + tid;
        int row = q >> 3, ch = q & 7;
        dA[i] = swz((uint32_t)(row * 128 + ch * 16));
        pA[i] = xh + (size_t)(m0 + row) * Kdim + ch * 8;
        pB[i] = wh + (size_t)(n0 + row) * Kdim + ch * 8;
    }

    // -------- accumulators --------
    float acc[4][4][4];
    #pragma unroll
    for (int mi = 0; mi < 4; mi++)
        #pragma unroll
        for (int ni = 0; ni < 4; ni++)
            #pragma unroll
            for (int j = 0; j < 4; j++)
                acc[mi][ni][j] = 0.0f;

    // -------- prologue: prefetch stages 0..STAGES-2 --------
    #pragma unroll
    for (int s = 0; s < STAGES - 1; s++) {
        const uint32_t sb_ = sbase + OFF_STAGE + s * STAGE_STRIDE;
        const int k0 = s * BK;
        #pragma unroll
        for (int i = 0; i < 4; i++) {
            cp16(sb_ + A_OFF + dA[i], pA[i] + k0);
            cp16(sb_ + B_OFF + dA[i], pB[i] + k0);
        }
        cp_commit();
    }

    // -------- mainloop --------
    const int mrow_base = wm * 64;
    const int nb_base   = wn * 32;

    // ldmatrix lane-invariant pieces (same mapping as R5, verified)
    const int a_row_in  = lane & 15;
    const int a_ksel    = lane >> 4;
    const int b_nrow_in = ((lane >> 4) << 3) + (lane & 7);
    const int b_ksel    = (lane >> 3) & 1;

    int st = 0;
    for (int kt = 0; kt < NKT; kt++) {
        cp_wait1();
        __syncthreads();

        // issue loads for kt+STAGES-1 into the stage freed last iteration
        {
            int kt_next = kt + STAGES - 1;
            if (kt_next < NKT) {
                int stn = st + (STAGES - 1); if (stn >= STAGES) stn -= STAGES;
                const uint32_t sb_ = sbase + OFF_STAGE + stn * STAGE_STRIDE;
                const int k0 = kt_next * BK;
                #pragma unroll
                for (int i = 0; i < 4; i++) {
                    cp16(sb_ + A_OFF + dA[i], pA[i] + k0);
                    cp16(sb_ + B_OFF + dA[i], pB[i] + k0);
                }
            }
            cp_commit(); // commit (possibly empty) to keep wait counts aligned
        }

        // consume stage st
        const uint32_t sA = sbase + OFF_STAGE + st * STAGE_STRIDE + A_OFF;
        const uint32_t sB = sbase + OFF_STAGE + st * STAGE_STRIDE + B_OFF;

        #pragma unroll
        for (int s = 0; s < 4; s++) {          // 4 k-steps of 16
            // ---- B fragments: 4 n-chunks of 8 ----
            uint32_t bfr[4][2];
            {
                uint32_t t[4];
                int nrow = nb_base + b_nrow_in;
                int ch = 2 * s + b_ksel;
                ldsm_x4(t, sB + (uint32_t)nrow * 128 + (uint32_t)((ch ^ (nrow & 7)) << 4));
                bfr[0][0] = t[0]; bfr[0][1] = t[1];
                bfr[1][0] = t[2]; bfr[1][1] = t[3];
                nrow += 16;
                ldsm_x4(t, sB + (uint32_t)nrow * 128 + (uint32_t)((ch ^ (nrow & 7)) << 4));
                bfr[2][0] = t[0]; bfr[2][1] = t[1];
                bfr[3][0] = t[2]; bfr[3][1] = t[3];
            }
            // ---- A, 4 m-chunks of 16 ----
            #pragma unroll
            for (int mi = 0; mi < 4; mi++) {
                int arow = mrow_base + mi * 16 + a_row_in;
                int ch = 2 * s + a_ksel;
                uint32_t off = (uint32_t)arow * 128 + (uint32_t)((ch ^ (arow & 7)) << 4);
                uint32_t af[4];
                ldsm_x4(af, sA + off);
                #pragma unroll
                for (int ni = 0; ni < 4; ni++)
                    mma16816(acc[mi][ni], af, bfr[ni]);
            }
        }

        st = (st + 1 == STAGES) ? 0 : st + 1;
    }

    // -------- epilogue: out = scale*acc + biasS --------
    const float sc = scale_p[0];
    const float* bs = reinterpret_cast<const float*>(smem + OFF_BIAS);
    const int gr = lane >> 2;
    const int gc = (lane & 3) * 2;
    #pragma unroll
    for (int mi = 0; mi < 4; mi++) {
        const int r = m0 + wm * 64 + mi * 16 + gr;
        #pragma unroll
        for (int ni = 0; ni < 4; ni++) {
            const int cl = wn * 32 + ni * 8 + gc;   // local col in [0,128)
            const int c  = n0 + cl;
            float2 v;
            v.x = fmaf(sc, acc[mi][ni][0], bs[cl]);
            v.y = fmaf(sc, acc[mi][ni][1], bs[cl + 1]);
            *reinterpret_cast<float2*>(out + (size_t)r * Ndim + c) = v;
            v.x = fmaf(sc, acc[mi][ni][2], bs[cl]);
            v.y = fmaf(sc, acc[mi][ni][3], bs[cl + 1]);
            *reinterpret_cast<float2*>(out + (size_t)(r + 8) * Ndim + c) = v;
        }
    }
}

// ---------------- launch ----------------
extern "C" void kernel_launch(void* const* d_in, const int* in_sizes, int n_in,
                              void* d_out, int out_size) {
    const float* x   = (const float*)d_in[0];
    const int*   qw  = (const int*)d_in[1];
    const int*   qb  = (const int*)d_in[2];
    const float* sc  = (const float*)d_in[3];
    const float* bsc = (const float*)d_in[4];
    float* out = (float*)d_out;

    convert_w_kernel<<<1184, 256>>>(qw);
    convert_x_kernel<<<1184, 256>>>(x);

    cudaFuncSetAttribute(gemm_kernel, cudaFuncAttributeMaxDynamicSharedMemorySize, SMEM_TOTAL);
    dim3 grid(Ndim / BN, Mdim / BM); // (128, 64)
    gemm_kernel<<<grid, 256, SMEM_TOTAL>>>(qb, sc, bsc, out);
}